// round 14
// baseline (speedup 1.0000x reference)
#include <cuda_runtime.h>
#include <cuda_bf16.h>
#include <cstdint>
#include <math.h>

// Problem constants
#define BATCH 16
#define C 256
#define HW 1024          // 32x32
#define HEADS 8
#define HDIM 32
#define M_TOTAL (BATCH * HW)   // 16384
#define KCONV (C * 9)          // 2304

// ---------------- scratch (static device globals; no runtime allocation) ---------
__device__ float g_w1t[KCONV * C];    // [r][c][n] bn1-folded conv1 weights (tf32)
__device__ float g_w2t[KCONV * C];
__device__ float g_b1[C];
__device__ float g_b2[C];
__device__ float g_wqkv[C * 768];     // [K=256][N=768] (q|k|v transposed, tf32)
__device__ float g_bqkv[768];
__device__ float g_wot[C * C];        // out_w transposed (tf32)
__device__ float g_t1[BATCH * C * HW];
__device__ float g_conv[BATCH * C * HW];
__device__ float g_qkv[BATCH * 768 * HW];
__device__ float g_attn[BATCH * C * HW];
// shifted copies: S_m1[q] = in[q-1], S_p1[q] = in[q+1], x-row-edge zeros
__device__ float g_xm1[BATCH * C * HW];
__device__ float g_xp1[BATCH * C * HW];
__device__ float g_t1m[BATCH * C * HW];   // edge cells never written -> stay 0
__device__ float g_t1p[BATCH * C * HW];

// ---------------- helpers ----------------
__device__ __forceinline__ float to_tf32(float x) {
    float y;
    asm("cvt.rna.tf32.f32 %0, %1;" : "=f"(y) : "f"(x));
    return y;
}

__device__ __forceinline__ void mma_tf32(float* c, const unsigned* a, const unsigned* b) {
    asm volatile(
        "mma.sync.aligned.m16n8k8.row.col.f32.tf32.tf32.f32 "
        "{%0,%1,%2,%3}, {%4,%5,%6,%7}, {%8,%9}, {%0,%1,%2,%3};\n"
        : "+f"(c[0]), "+f"(c[1]), "+f"(c[2]), "+f"(c[3])
        : "r"(a[0]), "r"(a[1]), "r"(a[2]), "r"(a[3]), "r"(b[0]), "r"(b[1]));
}

__device__ __forceinline__ void cp16(uint32_t s, const void* g) {
    asm volatile("cp.async.cg.shared.global [%0], [%1], 16;" :: "r"(s), "l"(g));
}
__device__ __forceinline__ void cp16_pred(uint32_t s, const void* g, bool ok) {
    int sz = ok ? 16 : 0;
    asm volatile("cp.async.cg.shared.global [%0], [%1], 16, %2;" :: "r"(s), "l"(g), "r"(sz));
}
__device__ __forceinline__ void cp_commit() { asm volatile("cp.async.commit_group;"); }
template<int N> __device__ __forceinline__ void cp_wait() {
    asm volatile("cp.async.wait_group %0;" :: "n"(N));
}

// fast exp on the FMA pipe. x <= 0 expected.
__device__ __forceinline__ float fast_exp(float x) {
    float t = x * 1.4426950408889634f;
    t = fmaxf(t, -126.0f);
    float fi = floorf(t);
    float f = t - fi;
    float p = fmaf(f, 0.0015041f, 0.0096181f);
    p = fmaf(f, p, 0.0555041f);
    p = fmaf(f, p, 0.2402265f);
    p = fmaf(f, p, 0.6931472f);
    p = fmaf(f, p, 1.0f);
    int e = (int)fi;
    return p * __int_as_float((e + 127) << 23);
}

// ---------------- x shift kernel ----------------
__global__ void xshift_kernel(const float* __restrict__ in,
                              float* __restrict__ om1, float* __restrict__ op1)
{
    int i = blockIdx.x * blockDim.x + threadIdx.x;
    if (i >= BATCH * C * HW) return;
    int col = i & 31;
    om1[i] = (col > 0)  ? in[i - 1] : 0.f;   // S_m1[q] = in[q-1]
    op1[i] = (col < 31) ? in[i + 1] : 0.f;   // S_p1[q] = in[q+1]
}

// ---------------- weight transform + BN fold ----------------
__global__ void prep_kernel(
    const float* __restrict__ conv1_w, const float* __restrict__ conv1_b,
    const float* __restrict__ g1, const float* __restrict__ be1,
    const float* __restrict__ m1, const float* __restrict__ v1,
    const float* __restrict__ conv2_w, const float* __restrict__ conv2_b,
    const float* __restrict__ g2, const float* __restrict__ be2,
    const float* __restrict__ m2, const float* __restrict__ v2,
    const float* __restrict__ q_w, const float* __restrict__ q_b,
    const float* __restrict__ k_w, const float* __restrict__ k_b,
    const float* __restrict__ v_w, const float* __restrict__ v_b,
    const float* __restrict__ o_w)
{
    const int W1T_N = KCONV * C;          // 589824
    const int QKV_N = C * 768;            // 196608
    const int WOT_N = C * C;              // 65536
    const int total = 2 * W1T_N + QKV_N + WOT_N + 768 + 512;
    for (int i = blockIdx.x * blockDim.x + threadIdx.x; i < total;
         i += gridDim.x * blockDim.x) {
        if (i < W1T_N) {
            int k = i >> 8, o = i & 255;       // k = r*256 + c
            int r = k >> 8, c = k & 255;
            float s = g1[o] * rsqrtf(v1[o] + 1e-5f);
            g_w1t[i] = to_tf32(conv1_w[(o * C + c) * 9 + r] * s);
        } else if (i < 2 * W1T_N) {
            int j = i - W1T_N;
            int k = j >> 8, o = j & 255;
            int r = k >> 8, c = k & 255;
            float s = g2[o] * rsqrtf(v2[o] + 1e-5f);
            g_w2t[j] = to_tf32(conv2_w[(o * C + c) * 9 + r] * s);
        } else if (i < 2 * W1T_N + QKV_N) {
            int j = i - 2 * W1T_N;
            int c = j / 768, n = j - c * 768;
            float w;
            if (n < 256)      w = q_w[n * C + c];
            else if (n < 512) w = k_w[(n - 256) * C + c];
            else              w = v_w[(n - 512) * C + c];
            g_wqkv[j] = to_tf32(w);
        } else if (i < 2 * W1T_N + QKV_N + WOT_N) {
            int j = i - (2 * W1T_N + QKV_N);
            int c = j >> 8, o = j & 255;
            g_wot[j] = to_tf32(o_w[o * C + c]);
        } else if (i < 2 * W1T_N + QKV_N + WOT_N + 768) {
            int n = i - (2 * W1T_N + QKV_N + WOT_N);
            float bb;
            if (n < 256)      bb = q_b[n];
            else if (n < 512) bb = k_b[n - 256];
            else              bb = v_b[n - 512];
            g_bqkv[n] = bb;
        } else {
            int j = i - (2 * W1T_N + QKV_N + WOT_N + 768); // 0..511
            int o = j & 255;
            if (j < 256) {
                float s = g1[o] * rsqrtf(v1[o] + 1e-5f);
                g_b1[o] = conv1_b[o] * s + be1[o] - m1[o] * s;
            } else {
                float s = g2[o] * rsqrtf(v2[o] + 1e-5f);
                g_b2[o] = conv2_b[o] * s + be2[o] - m2[o] * s;
            }
        }
    }
}

// ---------------- common tile params ----------------
#define BM 128
#define BN 128
#define BKT 32                    // 32-deep k-tile, 2-stage pipeline
#define AMS 136                   // 136 % 32 = 8 -> conflict-free fragment LDS
#define STAGE_F (BKT * AMS)       // 4352 floats per stage per matrix
#define GEMM_SMEM ((2 * STAGE_F * 2) * 4)   // 69632 B

// ---------------- 1x1 TF32 GEMM (qkv / out-proj), 2-stage cp.async ----------------
template<int EPI, int ROUND>
__global__ void __launch_bounds__(256, 2) gemm_k(
    const float* __restrict__ A, const float* __restrict__ Bw,
    const float* __restrict__ bias, float* __restrict__ Cout,
    int Kdim, int Ndim,
    const float* __restrict__ convres, const float* __restrict__ resid,
    const float* __restrict__ gp)
{
    extern __shared__ float dyn[];
    float* sA = dyn;
    float* sB = dyn + 2 * STAGE_F;

    const int tid  = threadIdx.x;
    const int lane = tid & 31;
    const int wid  = tid >> 5;
    const int wm   = wid & 1;
    const int wn   = wid >> 1;
    const int m0 = blockIdx.x * BM;
    const int n0 = blockIdx.y * BN;
    const int bq = m0 >> 10;
    const int p0 = m0 & 1023;

    const int sk  = tid >> 4;        // 0..15; rows sk and sk+16
    const int sm8 = (tid & 15) * 8;

    const uint32_t saA = (uint32_t)__cvta_generic_to_shared(sA);
    const uint32_t saB = (uint32_t)__cvta_generic_to_shared(sB);

    float acc[4][4][4];
#pragma unroll
    for (int i = 0; i < 4; i++)
#pragma unroll
        for (int j = 0; j < 4; j++)
#pragma unroll
            for (int q = 0; q < 4; q++) acc[i][j][q] = 0.f;

    const int nt = Kdim / BKT;

    auto stage = [&](int t, int st) {
#pragma unroll
        for (int r2 = 0; r2 < 2; r2++) {
            const int kr = sk + 16 * r2;
            const int k  = t * BKT + kr;
            uint32_t da = saA + (uint32_t)(st * STAGE_F + kr * AMS + sm8) * 4u;
            const float* ga = A + (((size_t)bq * C + k) << 10) + p0 + sm8;
            cp16(da, ga);
            cp16(da + 16, ga + 4);
            uint32_t db = saB + (uint32_t)(st * STAGE_F + kr * AMS + sm8) * 4u;
            const float* gb = Bw + (size_t)k * Ndim + n0 + sm8;
            cp16(db, gb);
            cp16(db + 16, gb + 4);
        }
        cp_commit();
    };

    stage(0, 0);

    for (int t = 0; t < nt; t++) {
        const int cur = t & 1;
        cp_wait<0>();
        __syncthreads();
        if (t + 1 < nt) stage(t + 1, cur ^ 1);

        const float* fA = sA + cur * STAGE_F;
        const float* fB = sB + cur * STAGE_F;
#pragma unroll
        for (int ks = 0; ks < 4; ks++) {
            const int kc = ks * 8 + (lane & 3);
            unsigned af[4][4], bf[4][2];
#pragma unroll
            for (int mi = 0; mi < 4; mi++) {
                int ar = wm * 64 + mi * 16 + (lane >> 2);
                af[mi][0] = __float_as_uint(fA[kc * AMS + ar]);
                af[mi][1] = __float_as_uint(fA[kc * AMS + ar + 8]);
                af[mi][2] = __float_as_uint(fA[(kc + 4) * AMS + ar]);
                af[mi][3] = __float_as_uint(fA[(kc + 4) * AMS + ar + 8]);
            }
#pragma unroll
            for (int nj = 0; nj < 4; nj++) {
                int br = wn * 32 + nj * 8 + (lane >> 2);
                bf[nj][0] = __float_as_uint(fB[kc * AMS + br]);
                bf[nj][1] = __float_as_uint(fB[(kc + 4) * AMS + br]);
            }
#pragma unroll
            for (int mi = 0; mi < 4; mi++)
#pragma unroll
                for (int nj = 0; nj < 4; nj++)
                    mma_tf32(acc[mi][nj], af[mi], bf[nj]);
        }
    }

    float sg = 0.f;
    if (EPI == 2) sg = 1.f / (1.f + __expf(-gp[0]));
#pragma unroll
    for (int mi = 0; mi < 4; mi++) {
#pragma unroll
        for (int half = 0; half < 2; half++) {
            int m = m0 + wm * 64 + mi * 16 + (lane >> 2) + half * 8;
            int mb = m >> 10, p = m & 1023;
#pragma unroll
            for (int nj = 0; nj < 4; nj++) {
                int n = n0 + wn * 32 + nj * 8 + 2 * (lane & 3);
                float v0 = acc[mi][nj][half * 2 + 0] + bias[n];
                float v1 = acc[mi][nj][half * 2 + 1] + bias[n + 1];
                size_t addr = (((size_t)mb * Ndim + n) << 10) + p;
                if (EPI == 2) {
                    float c0 = convres[addr], c1 = convres[addr + 1024];
                    float r0 = resid[addr],   r1 = resid[addr + 1024];
                    v0 = fmaxf(c0 + sg * v0 + r0, 0.f);
                    v1 = fmaxf(c1 + sg * v1 + r1, 0.f);
                }
                if (ROUND) { v0 = to_tf32(v0); v1 = to_tf32(v1); }
                Cout[addr]        = v0;
                Cout[addr + 1024] = v1;
            }
        }
    }
}

// ---------------- conv3x3 via pre-shifted inputs, 2-stage BKT=32 ----------------
// t = tap*8 + channel-tile(32ch); nt = 72
template<int EPI, int ROUND, int SHIFT>
__global__ void __launch_bounds__(256, 2) convgemm_k(
    const float* __restrict__ A0, const float* __restrict__ Am1,
    const float* __restrict__ Ap1,
    const float* __restrict__ Bw, const float* __restrict__ bias,
    float* __restrict__ Cout, float* __restrict__ Cm1, float* __restrict__ Cp1)
{
    extern __shared__ float dyn[];
    float* sA = dyn;
    float* sB = dyn + 2 * STAGE_F;

    const int tid  = threadIdx.x;
    const int lane = tid & 31;
    const int wid  = tid >> 5;
    const int wm   = wid & 1;
    const int wn   = wid >> 1;
    const int m0 = blockIdx.x * BM;
    const int n0 = blockIdx.y * BN;
    const int bq = m0 >> 10;
    const int p0 = m0 & 1023;

    const int sk  = tid >> 4;        // 0..15; rows sk and sk+16
    const int sm8 = (tid & 15) * 8;

    const uint32_t saA = (uint32_t)__cvta_generic_to_shared(sA);
    const uint32_t saB = (uint32_t)__cvta_generic_to_shared(sB);

    float acc[4][4][4];
#pragma unroll
    for (int i = 0; i < 4; i++)
#pragma unroll
        for (int j = 0; j < 4; j++)
#pragma unroll
            for (int q = 0; q < 4; q++) acc[i][j][q] = 0.f;

    const int nt = 72;   // 9 taps * 8 channel-tiles of 32

    auto stage = [&](int t, int st) {
        const int r   = t >> 3;          // tap 0..8
        const int ct  = t & 7;           // channel tile (32 ch)
        const int dy  = r / 3 - 1;
        const int dxi = r % 3;           // 0: dx=-1 -> Am1   1: dx=0 -> A0   2: dx=+1 -> Ap1
        const float* Ab = (dxi == 0) ? Am1 : (dxi == 1) ? A0 : Ap1;
        int y = ((p0 + sm8) >> 5) + dy;
        bool ok = ((unsigned)y < 32u);
#pragma unroll
        for (int r2 = 0; r2 < 2; r2++) {
            const int kr = sk + 16 * r2;
            const int c  = ct * 32 + kr;
            uint32_t da = saA + (uint32_t)(st * STAGE_F + kr * AMS + sm8) * 4u;
            const float* ga = ok ? (Ab + (((size_t)bq * C + c) << 10) + p0 + dy * 32 + sm8) : A0;
            cp16_pred(da, ga, ok);
            cp16_pred(da + 16, ga + 4, ok);
            uint32_t db = saB + (uint32_t)(st * STAGE_F + kr * AMS + sm8) * 4u;
            const float* gb = Bw + (size_t)(t * BKT + kr) * C + n0 + sm8;
            cp16(db, gb);
            cp16(db + 16, gb + 4);
        }
        cp_commit();
    };

    stage(0, 0);

    for (int t = 0; t < nt; t++) {
        const int cur = t & 1;
        cp_wait<0>();
        __syncthreads();
        if (t + 1 < nt) stage(t + 1, cur ^ 1);

        const float* fA = sA + cur * STAGE_F;
        const float* fB = sB + cur * STAGE_F;
#pragma unroll
        for (int ks = 0; ks < 4; ks++) {
            const int kc = ks * 8 + (lane & 3);
            unsigned af[4][4], bf[4][2];
#pragma unroll
            for (int mi = 0; mi < 4; mi++) {
                int ar = wm * 64 + mi * 16 + (lane >> 2);
                af[mi][0] = __float_as_uint(fA[kc * AMS + ar]);
                af[mi][1] = __float_as_uint(fA[kc * AMS + ar + 8]);
                af[mi][2] = __float_as_uint(fA[(kc + 4) * AMS + ar]);
                af[mi][3] = __float_as_uint(fA[(kc + 4) * AMS + ar + 8]);
            }
#pragma unroll
            for (int nj = 0; nj < 4; nj++) {
                int br = wn * 32 + nj * 8 + (lane >> 2);
                bf[nj][0] = __float_as_uint(fB[kc * AMS + br]);
                bf[nj][1] = __float_as_uint(fB[(kc + 4) * AMS + br]);
            }
#pragma unroll
            for (int mi = 0; mi < 4; mi++)
#pragma unroll
                for (int nj = 0; nj < 4; nj++)
                    mma_tf32(acc[mi][nj], af[mi], bf[nj]);
        }
    }

#pragma unroll
    for (int mi = 0; mi < 4; mi++) {
#pragma unroll
        for (int half = 0; half < 2; half++) {
            int m = m0 + wm * 64 + mi * 16 + (lane >> 2) + half * 8;
            int mb = m >> 10, p = m & 1023;
            int xcol = p & 31;
#pragma unroll
            for (int nj = 0; nj < 4; nj++) {
                int n = n0 + wn * 32 + nj * 8 + 2 * (lane & 3);
                float v0 = acc[mi][nj][half * 2 + 0] + bias[n];
                float v1 = acc[mi][nj][half * 2 + 1] + bias[n + 1];
                size_t addr = (((size_t)mb * C + n) << 10) + p;
                if (EPI == 1) { v0 = fmaxf(v0, 0.f); v1 = fmaxf(v1, 0.f); }
                if (ROUND) { v0 = to_tf32(v0); v1 = to_tf32(v1); }
                Cout[addr]        = v0;
                Cout[addr + 1024] = v1;
                if (SHIFT) {
                    if (xcol < 31) { Cm1[addr + 1] = v0; Cm1[addr + 1024 + 1] = v1; }
                    if (xcol > 0)  { Cp1[addr - 1] = v0; Cp1[addr + 1024 - 1] = v1; }
                }
            }
        }
    }
}

// ---------------- flash attention (TF32 mma, cp.async double-buffered) ----------
// block: 128 threads / 4 warps; 64 queries (16 per warp); loop 16 key-tiles of 64.
#define KS3 68    // sK/sV row stride
#define PS3 68    // sP row stride
#define KV_F (32 * KS3)                   // 2176 floats per tile
#define FATTN_SMEM ((4 * KV_F + 4 * 16 * PS3) * 4)   // 2xK + 2xV + P = 52224 B

__global__ void __launch_bounds__(128, 4) fattn_kernel(
    const float* __restrict__ qkv, float* __restrict__ out)
{
    extern __shared__ float fsm[];
    float* sK = fsm;                      // [2][32][KS3]
    float* sV = fsm + 2 * KV_F;           // [2][32][KS3]
    float* sP = fsm + 4 * KV_F;           // [4][16][PS3]

    const int tid  = threadIdx.x;
    const int lane = tid & 31;
    const int w    = tid >> 5;                 // 0..3
    const int q0   = blockIdx.x * 64 + w * 16; // warp query base
    const int h    = blockIdx.y;
    const int b    = blockIdx.z;

    const float* qbase = qkv + ((size_t)b * 768 + h * HDIM) * HW;
    const float* kbase = qbase + 256 * HW;
    const float* vbase = qbase + 512 * HW;

    const uint32_t saK = (uint32_t)__cvta_generic_to_shared(sK);
    const uint32_t saV = (uint32_t)__cvta_generic_to_shared(sV);

    const int qr = lane >> 2;
    const int qc = lane & 3;
    const float scale = 0.17677669529663687f;  // 1/sqrt(32)

    // Q fragments (pre-scaled; producer already tf32-rounded)
    unsigned aq[4][4];
#pragma unroll
    for (int ks = 0; ks < 4; ks++) {
        int dc = ks * 8 + qc;
        aq[ks][0] = __float_as_uint(to_tf32(qbase[dc * HW + q0 + qr] * scale));
        aq[ks][1] = __float_as_uint(to_tf32(qbase[dc * HW + q0 + qr + 8] * scale));
        aq[ks][2] = __float_as_uint(to_tf32(qbase[(dc + 4) * HW + q0 + qr] * scale));
        aq[ks][3] = __float_as_uint(to_tf32(qbase[(dc + 4) * HW + q0 + qr + 8] * scale));
    }

    // stage lambda: tile kt -> buffer st
    auto stage = [&](int kt, int st) {
#pragma unroll
        for (int i = tid; i < 512; i += 128) {
            int d = i >> 4, k4 = (i & 15) * 4;
            uint32_t off = (uint32_t)(st * KV_F + d * KS3 + k4) * 4u;
            cp16(saK + off, &kbase[d * HW + kt * 64 + k4]);
            cp16(saV + off, &vbase[d * HW + kt * 64 + k4]);
        }
        cp_commit();
    };

    float m0 = -1e30f, m1 = -1e30f;
    float l0 = 0.f,    l1 = 0.f;
    float cO[4][4];
#pragma unroll
    for (int nd = 0; nd < 4; nd++)
#pragma unroll
        for (int q = 0; q < 4; q++) cO[nd][q] = 0.f;

    float* myP = sP + w * 16 * PS3;

    stage(0, 0);

    for (int kt = 0; kt < 16; kt++) {
        const int cur = kt & 1;
        cp_wait<0>();
        __syncthreads();
        if (kt + 1 < 16) stage(kt + 1, cur ^ 1);

        const float* fK = sK + cur * KV_F;
        const float* fV = sV + cur * KV_F;

        // S = Q K : 16q x 64k
        float cS[8][4];
#pragma unroll
        for (int nj = 0; nj < 8; nj++)
#pragma unroll
            for (int q = 0; q < 4; q++) cS[nj][q] = 0.f;
#pragma unroll
        for (int ks = 0; ks < 4; ks++) {
            int dc = ks * 8 + qc;
#pragma unroll
            for (int nj = 0; nj < 8; nj++) {
                int ncol = nj * 8 + qr;
                unsigned bf[2];
                bf[0] = __float_as_uint(fK[dc * KS3 + ncol]);
                bf[1] = __float_as_uint(fK[(dc + 4) * KS3 + ncol]);
                mma_tf32(cS[nj], aq[ks], bf);
            }
        }

        // row max over tile
        float t0 = -1e30f, t1 = -1e30f;
#pragma unroll
        for (int nj = 0; nj < 8; nj++) {
            t0 = fmaxf(t0, fmaxf(cS[nj][0], cS[nj][1]));
            t1 = fmaxf(t1, fmaxf(cS[nj][2], cS[nj][3]));
        }
        t0 = fmaxf(t0, __shfl_xor_sync(0xffffffffu, t0, 1));
        t0 = fmaxf(t0, __shfl_xor_sync(0xffffffffu, t0, 2));
        t1 = fmaxf(t1, __shfl_xor_sync(0xffffffffu, t1, 1));
        t1 = fmaxf(t1, __shfl_xor_sync(0xffffffffu, t1, 2));

        float mn0 = fmaxf(m0, t0), mn1 = fmaxf(m1, t1);
        float cor0 = fast_exp(m0 - mn0), cor1 = fast_exp(m1 - mn1);
        m0 = mn0; m1 = mn1;

        float s0 = 0.f, s1 = 0.f;
#pragma unroll
        for (int nj = 0; nj < 8; nj++) {
            float p00 = fast_exp(cS[nj][0] - m0);
            float p01 = fast_exp(cS[nj][1] - m0);
            float p10 = fast_exp(cS[nj][2] - m1);
            float p11 = fast_exp(cS[nj][3] - m1);
            s0 += p00 + p01;
            s1 += p10 + p11;
            int colp = nj * 8 + 2 * qc;
            myP[qr * PS3 + colp]           = to_tf32(p00);
            myP[qr * PS3 + colp + 1]       = to_tf32(p01);
            myP[(qr + 8) * PS3 + colp]     = to_tf32(p10);
            myP[(qr + 8) * PS3 + colp + 1] = to_tf32(p11);
        }
        s0 += __shfl_xor_sync(0xffffffffu, s0, 1);
        s0 += __shfl_xor_sync(0xffffffffu, s0, 2);
        s1 += __shfl_xor_sync(0xffffffffu, s1, 1);
        s1 += __shfl_xor_sync(0xffffffffu, s1, 2);
        l0 = l0 * cor0 + s0;
        l1 = l1 * cor1 + s1;

        // rescale O
#pragma unroll
        for (int nd = 0; nd < 4; nd++) {
            cO[nd][0] *= cor0; cO[nd][1] *= cor0;
            cO[nd][2] *= cor1; cO[nd][3] *= cor1;
        }
        __syncwarp();

        // O += P V   (P: 16q x 64k via smem relayout; V: 64k x 32d)
#pragma unroll
        for (int ksp = 0; ksp < 8; ksp++) {
            int pc = ksp * 8 + qc;
            unsigned aP[4];
            aP[0] = __float_as_uint(myP[qr * PS3 + pc]);
            aP[1] = __float_as_uint(myP[(qr + 8) * PS3 + pc]);
            aP[2] = __float_as_uint(myP[qr * PS3 + pc + 4]);
            aP[3] = __float_as_uint(myP[(qr + 8) * PS3 + pc + 4]);
#pragma unroll
            for (int nd = 0; nd < 4; nd++) {
                int dc = nd * 8 + qr;
                unsigned bf[2];
                bf[0] = __float_as_uint(fV[dc * KS3 + pc]);
                bf[1] = __float_as_uint(fV[dc * KS3 + pc + 4]);
                mma_tf32(cO[nd], aP, bf);
            }
        }
        __syncwarp();
    }

    // normalize + write (tf32-rounded, consumed by out-proj GEMM)
    float il0 = 1.f / l0, il1 = 1.f / l1;
    size_t obase = ((size_t)b * C + h * HDIM) * HW;
#pragma unroll
    for (int nd = 0; nd < 4; nd++) {
        int d = nd * 8 + 2 * qc;
        out[obase + (size_t)d * HW + q0 + qr]            = to_tf32(cO[nd][0] * il0);
        out[obase + (size_t)(d + 1) * HW + q0 + qr]      = to_tf32(cO[nd][1] * il0);
        out[obase + (size_t)d * HW + q0 + qr + 8]        = to_tf32(cO[nd][2] * il1);
        out[obase + (size_t)(d + 1) * HW + q0 + qr + 8]  = to_tf32(cO[nd][3] * il1);
    }
}

// ---------------- launch ----------------
extern "C" void kernel_launch(void* const* d_in, const int* in_sizes, int n_in,
                              void* d_out, int out_size)
{
    const float* x       = (const float*)d_in[0];
    const float* conv1_w = (const float*)d_in[1];
    const float* conv1_b = (const float*)d_in[2];
    const float* bn1_g   = (const float*)d_in[3];
    const float* bn1_b   = (const float*)d_in[4];
    const float* bn1_m   = (const float*)d_in[5];
    const float* bn1_v   = (const float*)d_in[6];
    const float* conv2_w = (const float*)d_in[7];
    const float* conv2_b = (const float*)d_in[8];
    const float* bn2_g   = (const float*)d_in[9];
    const float* bn2_b   = (const float*)d_in[10];
    const float* bn2_m   = (const float*)d_in[11];
    const float* bn2_v   = (const float*)d_in[12];
    const float* q_w     = (const float*)d_in[13];
    const float* q_b     = (const float*)d_in[14];
    const float* k_w     = (const float*)d_in[15];
    const float* k_b     = (const float*)d_in[16];
    const float* v_w     = (const float*)d_in[17];
    const float* v_b     = (const float*)d_in[18];
    const float* o_w     = (const float*)d_in[19];
    const float* o_b     = (const float*)d_in[20];
    const float* gate    = (const float*)d_in[21];
    float* out           = (float*)d_out;

    float *p_w1t, *p_w2t, *p_b1, *p_b2, *p_wqkv, *p_bqkv, *p_wot;
    float *p_t1, *p_conv, *p_qkv, *p_attn;
    float *p_xm1, *p_xp1, *p_t1m, *p_t1p;
    cudaGetSymbolAddress((void**)&p_w1t,  g_w1t);
    cudaGetSymbolAddress((void**)&p_w2t,  g_w2t);
    cudaGetSymbolAddress((void**)&p_b1,   g_b1);
    cudaGetSymbolAddress((void**)&p_b2,   g_b2);
    cudaGetSymbolAddress((void**)&p_wqkv, g_wqkv);
    cudaGetSymbolAddress((void**)&p_bqkv, g_bqkv);
    cudaGetSymbolAddress((void**)&p_wot,  g_wot);
    cudaGetSymbolAddress((void**)&p_t1,   g_t1);
    cudaGetSymbolAddress((void**)&p_conv, g_conv);
    cudaGetSymbolAddress((void**)&p_qkv,  g_qkv);
    cudaGetSymbolAddress((void**)&p_attn, g_attn);
    cudaGetSymbolAddress((void**)&p_xm1,  g_xm1);
    cudaGetSymbolAddress((void**)&p_xp1,  g_xp1);
    cudaGetSymbolAddress((void**)&p_t1m,  g_t1m);
    cudaGetSymbolAddress((void**)&p_t1p,  g_t1p);

    static cudaStream_t s_side = nullptr;
    static cudaEvent_t ev_fork = nullptr, ev_join = nullptr;
    static bool attrs_set = false;
    if (s_side == nullptr) {
        cudaStreamCreateWithFlags(&s_side, cudaStreamNonBlocking);
        cudaEventCreateWithFlags(&ev_fork, cudaEventDisableTiming);
        cudaEventCreateWithFlags(&ev_join, cudaEventDisableTiming);
    }
    if (!attrs_set) {
        cudaFuncSetAttribute(gemm_k<0, 1>, cudaFuncAttributeMaxDynamicSharedMemorySize, GEMM_SMEM);
        cudaFuncSetAttribute(gemm_k<2, 0>, cudaFuncAttributeMaxDynamicSharedMemorySize, GEMM_SMEM);
        cudaFuncSetAttribute(convgemm_k<1, 1, 1>, cudaFuncAttributeMaxDynamicSharedMemorySize, GEMM_SMEM);
        cudaFuncSetAttribute(convgemm_k<0, 0, 0>, cudaFuncAttributeMaxDynamicSharedMemorySize, GEMM_SMEM);
        cudaFuncSetAttribute(fattn_kernel, cudaFuncAttributeMaxDynamicSharedMemorySize, FATTN_SMEM);
        attrs_set = true;
    }

    // side stream: shifted copies of x (no dependencies)
    xshift_kernel<<<(BATCH * C * HW) / 256, 256, 0, s_side>>>(x, p_xm1, p_xp1);

    // main: weight transform + BN fold
    prep_kernel<<<1024, 256>>>(conv1_w, conv1_b, bn1_g, bn1_b, bn1_m, bn1_v,
                               conv2_w, conv2_b, bn2_g, bn2_b, bn2_m, bn2_v,
                               q_w, q_b, k_w, k_b, v_w, v_b, o_w);

    // fork: conv chain on side stream (after prep)
    cudaEventRecord(ev_fork, 0);
    cudaStreamWaitEvent(s_side, ev_fork, 0);

    dim3 gConv(M_TOTAL / BM, C / BN);
    convgemm_k<1, 1, 1><<<gConv, 256, GEMM_SMEM, s_side>>>(
        x, p_xm1, p_xp1, p_w1t, p_b1, p_t1, p_t1m, p_t1p);
    convgemm_k<0, 0, 0><<<gConv, 256, GEMM_SMEM, s_side>>>(
        p_t1, p_t1m, p_t1p, p_w2t, p_b2, p_conv, nullptr, nullptr);
    cudaEventRecord(ev_join, s_side);

    // main stream: qkv -> flash attention
    dim3 gQKV(M_TOTAL / BM, 768 / BN);
    gemm_k<0, 1><<<gQKV, 256, GEMM_SMEM>>>(x, p_wqkv, p_bqkv, p_qkv, C, 768,
                                           nullptr, nullptr, nullptr);
    dim3 gAttn(HW / 64, HEADS, BATCH);
    fattn_kernel<<<gAttn, 128, FATTN_SMEM>>>(p_qkv, p_attn);

    // join, then fused epilogue GEMM
    cudaStreamWaitEvent(0, ev_join, 0);
    dim3 gOut(M_TOTAL / BM, C / BN);
    gemm_k<2, 0><<<gOut, 256, GEMM_SMEM>>>(p_attn, p_wot, o_b, out, C, C,
                                           p_conv, x, gate);
}

// round 16
// speedup vs baseline: 1.2655x; 1.2655x over previous
#include <cuda_runtime.h>
#include <cuda_fp16.h>
#include <cstdint>
#include <math.h>

#define BATCH 16
#define C 256
#define HW 1024
#define HEADS 8
#define HDIM 32
#define M_TOTAL (BATCH * HW)
#define KCONV (C * 9)
#define NB (BATCH * C * HW)
#define NPAIR (NB / 2)

__device__ float g_b1[C];
__device__ float g_b2[C];
__device__ float g_wqkv[C * 768];
__device__ float g_bqkv[768];
__device__ float g_wot[C * C];
__device__ float g_conv[NB];
__device__ float g_qkv[BATCH * 768 * HW];
__device__ float g_attn[NB];
__device__ __align__(16) __half g_w1f[C * KCONV];
__device__ __align__(16) __half g_w2f[C * KCONV];
__device__ __align__(16) __half g_t1f[NB];
// paired u32 buffers: [bq][cpair][sp] holding {v[2c][sp], v[2c+1][sp]} as half2
__device__ __align__(16) uint32_t g_px0[NPAIR];
__device__ __align__(16) uint32_t g_pxm[NPAIR];
__device__ __align__(16) uint32_t g_pxp[NPAIR];
__device__ __align__(16) uint32_t g_pt0[NPAIR];
__device__ __align__(16) uint32_t g_ptm[NPAIR];
__device__ __align__(16) uint32_t g_ptp[NPAIR];

__device__ __forceinline__ float to_tf32(float x){float y;asm("cvt.rna.tf32.f32 %0,%1;":"=f"(y):"f"(x));return y;}
__device__ __forceinline__ void mma_tf32(float* c,const unsigned* a,const unsigned* b){
    asm volatile("mma.sync.aligned.m16n8k8.row.col.f32.tf32.tf32.f32 {%0,%1,%2,%3},{%4,%5,%6,%7},{%8,%9},{%0,%1,%2,%3};\n"
    :"+f"(c[0]),"+f"(c[1]),"+f"(c[2]),"+f"(c[3]):"r"(a[0]),"r"(a[1]),"r"(a[2]),"r"(a[3]),"r"(b[0]),"r"(b[1]));}
__device__ __forceinline__ void mma_f16(float* c,const unsigned* a,const unsigned* b){
    asm volatile("mma.sync.aligned.m16n8k16.row.col.f32.f16.f16.f32 {%0,%1,%2,%3},{%4,%5,%6,%7},{%8,%9},{%0,%1,%2,%3};\n"
    :"+f"(c[0]),"+f"(c[1]),"+f"(c[2]),"+f"(c[3]):"r"(a[0]),"r"(a[1]),"r"(a[2]),"r"(a[3]),"r"(b[0]),"r"(b[1]));}
__device__ __forceinline__ void cp16(uint32_t s,const void* g){asm volatile("cp.async.cg.shared.global [%0],[%1],16;"::"r"(s),"l"(g));}
__device__ __forceinline__ void cp16_pred(uint32_t s,const void* g,bool ok){int sz=ok?16:0;
    asm volatile("cp.async.cg.shared.global [%0],[%1],16,%2;"::"r"(s),"l"(g),"r"(sz));}
__device__ __forceinline__ void cp_commit(){asm volatile("cp.async.commit_group;");}
template<int N> __device__ __forceinline__ void cp_wait(){asm volatile("cp.async.wait_group %0;"::"n"(N));}
__device__ __forceinline__ float fast_exp(float x){
    float t=x*1.4426950408889634f; t=fmaxf(t,-126.0f);
    float fi=floorf(t), f=t-fi;
    float p=fmaf(f,0.0015041f,0.0096181f); p=fmaf(f,p,0.0555041f); p=fmaf(f,p,0.2402265f);
    p=fmaf(f,p,0.6931472f); p=fmaf(f,p,1.0f);
    return p*__int_as_float(((int)fi+127)<<23);}
__device__ __forceinline__ uint32_t pkh(__half a,__half b){
    return (uint32_t)__half_as_ushort(a)|((uint32_t)__half_as_ushort(b)<<16);}

// ---- pack x (fp32) into 3 paired-fp16 buffers ----
__global__ void xpack_kernel(const float* __restrict__ x){
    int i=blockIdx.x*blockDim.x+threadIdx.x; if(i>=NPAIR) return;
    int bq=i>>17, cp=(i>>10)&127, sp=i&1023, col=sp&31;
    size_t r0=((size_t)(bq*C+2*cp))<<10;
    g_px0[i]=pkh(__float2half(x[r0+sp]),__float2half(x[r0+1024+sp]));
    g_pxm[i]=(col>0)?pkh(__float2half(x[r0+sp-1]),__float2half(x[r0+1024+sp-1])):0u;
    g_pxp[i]=(col<31)?pkh(__float2half(x[r0+sp+1]),__float2half(x[r0+1024+sp+1])):0u;
}
// ---- repack t1 (plain fp16) into 3 paired buffers ----
__global__ void tpack_kernel(const __half* __restrict__ t){
    int i=blockIdx.x*blockDim.x+threadIdx.x; if(i>=NPAIR) return;
    int bq=i>>17, cp=(i>>10)&127, sp=i&1023, col=sp&31;
    size_t r0=((size_t)(bq*C+2*cp))<<10;
    g_pt0[i]=pkh(t[r0+sp],t[r0+1024+sp]);
    g_ptm[i]=(col>0)?pkh(t[r0+sp-1],t[r0+1024+sp-1]):0u;
    g_ptp[i]=(col<31)?pkh(t[r0+sp+1],t[r0+1024+sp+1]):0u;
}

__global__ void prep_kernel(
    const float* __restrict__ c1w,const float* __restrict__ c1b,
    const float* __restrict__ g1,const float* __restrict__ be1,
    const float* __restrict__ m1,const float* __restrict__ v1,
    const float* __restrict__ c2w,const float* __restrict__ c2b,
    const float* __restrict__ g2,const float* __restrict__ be2,
    const float* __restrict__ m2,const float* __restrict__ v2,
    const float* __restrict__ q_w,const float* __restrict__ q_b,
    const float* __restrict__ k_w,const float* __restrict__ k_b,
    const float* __restrict__ v_w,const float* __restrict__ v_b,
    const float* __restrict__ o_w)
{
    const int WBF=C*KCONV, QKV_N=C*768, WOT_N=C*C;
    const int total=2*WBF+QKV_N+WOT_N+768+512;
    for(int i=blockIdx.x*blockDim.x+threadIdx.x;i<total;i+=gridDim.x*blockDim.x){
        if(i<WBF){
            int cout=i/KCONV, kk=i%KCONV, tap=kk>>8, c=kk&255;
            float s=g1[cout]*rsqrtf(v1[cout]+1e-5f);
            g_w1f[i]=__float2half(c1w[(cout*C+c)*9+tap]*s);
        } else if(i<2*WBF){
            int j=i-WBF, cout=j/KCONV, kk=j%KCONV, tap=kk>>8, c=kk&255;
            float s=g2[cout]*rsqrtf(v2[cout]+1e-5f);
            g_w2f[j]=__float2half(c2w[(cout*C+c)*9+tap]*s);
        } else if(i<2*WBF+QKV_N){
            int j=i-2*WBF, c=j/768, n=j-c*768; float w;
            if(n<256)w=q_w[n*C+c]; else if(n<512)w=k_w[(n-256)*C+c]; else w=v_w[(n-512)*C+c];
            g_wqkv[j]=to_tf32(w);
        } else if(i<2*WBF+QKV_N+WOT_N){
            int j=i-(2*WBF+QKV_N); int c=j>>8,o=j&255; g_wot[j]=to_tf32(o_w[o*C+c]);
        } else if(i<2*WBF+QKV_N+WOT_N+768){
            int n=i-(2*WBF+QKV_N+WOT_N); float bb;
            if(n<256)bb=q_b[n]; else if(n<512)bb=k_b[n-256]; else bb=v_b[n-512];
            g_bqkv[n]=bb;
        } else {
            int j=i-(2*WBF+QKV_N+WOT_N+768), o=j&255;
            if(j<256){float s=g1[o]*rsqrtf(v1[o]+1e-5f); g_b1[o]=c1b[o]*s+be1[o]-m1[o]*s;}
            else     {float s=g2[o]*rsqrtf(v2[o]+1e-5f); g_b2[o]=c2b[o]*s+be2[o]-m2[o]*s;}
        }
    }
}

// ---------------- fp16 conv3x3 GEMM: M=cout 128, N=spatial 128, K=2304 ----------
// A = weights [cout][k] fp16 (k pairs contiguous); B = paired activations
// [cpair][sp] u32 (half2 {v[2c],v[2c+1]}); 72 k-tiles (tap*8 + 32ch tile).
// smem: A [128 rows][20 u32]; B [16 kp][136 u32]; 2-stage.
#define CSTU 4736                          // u32 per stage (2560 + 2176)
#define CONV_SMEM (2 * CSTU * 4)           // 37888 B
template<int EPI>
__global__ void __launch_bounds__(256,2) convf16_k(
    const __half* __restrict__ Wf,
    const uint32_t* __restrict__ B0, const uint32_t* __restrict__ Bm,
    const uint32_t* __restrict__ Bp,
    const float* __restrict__ bias,
    float* __restrict__ outF, __half* __restrict__ outH)
{
    extern __shared__ __align__(16) uint32_t smu[];
    const uint32_t sbase=(uint32_t)__cvta_generic_to_shared(smu);
    const int tid=threadIdx.x, lane=tid&31, wid=tid>>5;
    const int wm=wid&1, wn=wid>>1;
    const int bq=blockIdx.x>>3, p0=(blockIdx.x&7)*128;
    const int cm0=blockIdx.y*128;

    float acc[4][4][4];
#pragma unroll
    for(int i=0;i<4;i++)
#pragma unroll
        for(int j=0;j<4;j++)
#pragma unroll
            for(int q=0;q<4;q++) acc[i][j][q]=0.f;

    auto stage=[&](int t,int st){
        const int tap=t>>3, ct=t&7, dy=tap/3-1, dxi=tap%3;
        const uint32_t* Bb=(dxi==0)?Bm:(dxi==1)?B0:Bp;
        const int cp0=ct*16;
        const int koff=tap*256+ct*32;
        uint32_t sa=sbase+st*CSTU*4;
        uint32_t sb=sa+2560*4;
#pragma unroll
        for(int r=0;r<2;r++){                  // A: 512 cp16
            int i=tid*2+r, row=i>>2, j=i&3;
            cp16(sa+(row*20+j*4)*4, Wf+(size_t)(cm0+row)*KCONV+koff+j*8);
        }
#pragma unroll
        for(int r=0;r<2;r++){                  // B: 512 cp16
            int i=tid*2+r, row=i>>5, j=i&31;
            int spb=p0+j*4;
            int y=(spb>>5)+dy;
            bool ok=((unsigned)y<32u);
            const uint32_t* src=Bb+(((size_t)bq*128+cp0+row)<<10)+spb+dy*32;
            cp16_pred(sb+(row*136+j*4)*4, src, ok);
        }
        cp_commit();
    };

    stage(0,0);
    const int nt=72;
    for(int t=0;t<nt;t++){
        const int cur=t&1;
        cp_wait<0>(); __syncthreads();
        if(t+1<nt) stage(t+1,cur^1);
        const uint32_t* fA=smu+cur*CSTU;
        const uint32_t* fB=fA+2560;
#pragma unroll
        for(int ks=0;ks<2;ks++){
            const int kp=ks*8+(lane&3);
            unsigned af[4][4], bf[4][2];
#pragma unroll
            for(int mi=0;mi<4;mi++){
                int ar=wm*64+mi*16+(lane>>2);
                af[mi][0]=fA[ar*20+kp];
                af[mi][1]=fA[(ar+8)*20+kp];
                af[mi][2]=fA[ar*20+kp+4];
                af[mi][3]=fA[(ar+8)*20+kp+4];
            }
#pragma unroll
            for(int nj=0;nj<4;nj++){
                int nc=wn*32+nj*8+(lane>>2);
                bf[nj][0]=fB[kp*136+nc];
                bf[nj][1]=fB[(kp+4)*136+nc];
            }
#pragma unroll
            for(int mi=0;mi<4;mi++)
#pragma unroll
                for(int nj=0;nj<4;nj++)
                    mma_f16(acc[mi][nj],af[mi],bf[nj]);
        }
    }

#pragma unroll
    for(int mi=0;mi<4;mi++){
#pragma unroll
        for(int half=0;half<2;half++){
            int cout=cm0+wm*64+mi*16+(lane>>2)+half*8;
            float bv=bias[cout];
            size_t rbase=(((size_t)bq*C+cout)<<10)+p0;
#pragma unroll
            for(int nj=0;nj<4;nj++){
                int spl=wn*32+nj*8+2*(lane&3);
                float v0=acc[mi][nj][half*2+0]+bv;
                float v1=acc[mi][nj][half*2+1]+bv;
                if(EPI==1){
                    v0=fmaxf(v0,0.f); v1=fmaxf(v1,0.f);
                    *(uint32_t*)&outH[rbase+spl]=pkh(__float2half(v0),__float2half(v1));
                } else {
                    float2 o; o.x=v0; o.y=v1;
                    *(float2*)&outF[rbase+spl]=o;
                }
            }
        }
    }
}

// ---------------- tf32 GEMM (qkv / out-proj) + flash attention (proven) ---------
#define BM 128
#define BN 128
#define BKT 32
#define AMS 136
#define STAGE_F (BKT * AMS)
#define GEMM_SMEM ((2 * STAGE_F * 2) * 4)

template<int EPI, int ROUND>
__global__ void __launch_bounds__(256, 2) gemm_k(
    const float* __restrict__ A, const float* __restrict__ Bw,
    const float* __restrict__ bias, float* __restrict__ Cout,
    int Kdim, int Ndim,
    const float* __restrict__ convres, const float* __restrict__ resid,
    const float* __restrict__ gp)
{
    extern __shared__ float dyn[];
    float* sA = dyn;
    float* sB = dyn + 2 * STAGE_F;
    const int tid=threadIdx.x, lane=tid&31, wid=tid>>5, wm=wid&1, wn=wid>>1;
    const int m0=blockIdx.x*BM, n0=blockIdx.y*BN, bq=m0>>10, p0=m0&1023;
    const int sk=tid>>4, sm8=(tid&15)*8;
    const uint32_t saA=(uint32_t)__cvta_generic_to_shared(sA);
    const uint32_t saB=(uint32_t)__cvta_generic_to_shared(sB);
    float acc[4][4][4];
#pragma unroll
    for(int i=0;i<4;i++)
#pragma unroll
        for(int j=0;j<4;j++)
#pragma unroll
            for(int q=0;q<4;q++) acc[i][j][q]=0.f;
    const int nt=Kdim/BKT;
    auto stage=[&](int t,int st){
#pragma unroll
        for(int r2=0;r2<2;r2++){
            const int kr=sk+16*r2, k=t*BKT+kr;
            uint32_t da=saA+(uint32_t)(st*STAGE_F+kr*AMS+sm8)*4u;
            const float* ga=A+(((size_t)bq*C+k)<<10)+p0+sm8;
            cp16(da,ga); cp16(da+16,ga+4);
            uint32_t db=saB+(uint32_t)(st*STAGE_F+kr*AMS+sm8)*4u;
            const float* gb=Bw+(size_t)k*Ndim+n0+sm8;
            cp16(db,gb); cp16(db+16,gb+4);
        }
        cp_commit();
    };
    stage(0,0);
    for(int t=0;t<nt;t++){
        const int cur=t&1;
        cp_wait<0>(); __syncthreads();
        if(t+1<nt) stage(t+1,cur^1);
        const float* fA=sA+cur*STAGE_F;
        const float* fB=sB+cur*STAGE_F;
#pragma unroll
        for(int ks=0;ks<4;ks++){
            const int kc=ks*8+(lane&3);
            unsigned af[4][4], bf[4][2];
#pragma unroll
            for(int mi=0;mi<4;mi++){
                int ar=wm*64+mi*16+(lane>>2);
                af[mi][0]=__float_as_uint(fA[kc*AMS+ar]);
                af[mi][1]=__float_as_uint(fA[kc*AMS+ar+8]);
                af[mi][2]=__float_as_uint(fA[(kc+4)*AMS+ar]);
                af[mi][3]=__float_as_uint(fA[(kc+4)*AMS+ar+8]);
            }
#pragma unroll
            for(int nj=0;nj<4;nj++){
                int br=wn*32+nj*8+(lane>>2);
                bf[nj][0]=__float_as_uint(fB[kc*AMS+br]);
                bf[nj][1]=__float_as_uint(fB[(kc+4)*AMS+br]);
            }
#pragma unroll
            for(int mi=0;mi<4;mi++)
#pragma unroll
                for(int nj=0;nj<4;nj++) mma_tf32(acc[mi][nj],af[mi],bf[nj]);
        }
    }
    float sg=0.f;
    if(EPI==2) sg=1.f/(1.f+__expf(-gp[0]));
#pragma unroll
    for(int mi=0;mi<4;mi++){
#pragma unroll
        for(int half=0;half<2;half++){
            int m=m0+wm*64+mi*16+(lane>>2)+half*8;
            int mb=m>>10, p=m&1023;
#pragma unroll
            for(int nj=0;nj<4;nj++){
                int n=n0+wn*32+nj*8+2*(lane&3);
                float v0=acc[mi][nj][half*2+0]+bias[n];
                float v1=acc[mi][nj][half*2+1]+bias[n+1];
                size_t addr=(((size_t)mb*Ndim+n)<<10)+p;
                if(EPI==2){
                    float c0=convres[addr], c1=convres[addr+1024];
                    float r0=resid[addr], r1=resid[addr+1024];
                    v0=fmaxf(c0+sg*v0+r0,0.f); v1=fmaxf(c1+sg*v1+r1,0.f);
                }
                if(ROUND){v0=to_tf32(v0);v1=to_tf32(v1);}
                Cout[addr]=v0; Cout[addr+1024]=v1;
            }
        }
    }
}

#define KS3 68
#define PS3 68
#define KV_F (32 * KS3)
#define FATTN_SMEM ((4 * KV_F + 4 * 16 * PS3) * 4)

__global__ void __launch_bounds__(128, 4) fattn_kernel(
    const float* __restrict__ qkv, float* __restrict__ out)
{
    extern __shared__ float fsm[];
    float* sK=fsm; float* sV=fsm+2*KV_F; float* sP=fsm+4*KV_F;
    const int tid=threadIdx.x, lane=tid&31, w=tid>>5;
    const int q0=blockIdx.x*64+w*16, h=blockIdx.y, b=blockIdx.z;
    const float* qbase=qkv+((size_t)b*768+h*HDIM)*HW;
    const float* kbase=qbase+256*HW;
    const float* vbase=qbase+512*HW;
    const uint32_t saK=(uint32_t)__cvta_generic_to_shared(sK);
    const uint32_t saV=(uint32_t)__cvta_generic_to_shared(sV);
    const int qr=lane>>2, qc=lane&3;
    const float scale=0.17677669529663687f;
    unsigned aq[4][4];
#pragma unroll
    for(int ks=0;ks<4;ks++){
        int dc=ks*8+qc;
        aq[ks][0]=__float_as_uint(to_tf32(qbase[dc*HW+q0+qr]*scale));
        aq[ks][1]=__float_as_uint(to_tf32(qbase[dc*HW+q0+qr+8]*scale));
        aq[ks][2]=__float_as_uint(to_tf32(qbase[(dc+4)*HW+q0+qr]*scale));
        aq[ks][3]=__float_as_uint(to_tf32(qbase[(dc+4)*HW+q0+qr+8]*scale));
    }
    auto stage=[&](int kt,int st){
#pragma unroll
        for(int i=tid;i<512;i+=128){
            int d=i>>4, k4=(i&15)*4;
            uint32_t off=(uint32_t)(st*KV_F+d*KS3+k4)*4u;
            cp16(saK+off,&kbase[d*HW+kt*64+k4]);
            cp16(saV+off,&vbase[d*HW+kt*64+k4]);
        }
        cp_commit();
    };
    float m0=-1e30f,m1=-1e30f,l0=0.f,l1=0.f;
    float cO[4][4];
#pragma unroll
    for(int nd=0;nd<4;nd++)
#pragma unroll
        for(int q=0;q<4;q++) cO[nd][q]=0.f;
    float* myP=sP+w*16*PS3;
    stage(0,0);
    for(int kt=0;kt<16;kt++){
        const int cur=kt&1;
        cp_wait<0>(); __syncthreads();
        if(kt+1<16) stage(kt+1,cur^1);
        const float* fK=sK+cur*KV_F;
        const float* fV=sV+cur*KV_F;
        float cS[8][4];
#pragma unroll
        for(int nj=0;nj<8;nj++)
#pragma unroll
            for(int q=0;q<4;q++) cS[nj][q]=0.f;
#pragma unroll
        for(int ks=0;ks<4;ks++){
            int dc=ks*8+qc;
#pragma unroll
            for(int nj=0;nj<8;nj++){
                int ncol=nj*8+qr;
                unsigned bf[2];
                bf[0]=__float_as_uint(fK[dc*KS3+ncol]);
                bf[1]=__float_as_uint(fK[(dc+4)*KS3+ncol]);
                mma_tf32(cS[nj],aq[ks],bf);
            }
        }
        float t0=-1e30f,t1=-1e30f;
#pragma unroll
        for(int nj=0;nj<8;nj++){
            t0=fmaxf(t0,fmaxf(cS[nj][0],cS[nj][1]));
            t1=fmaxf(t1,fmaxf(cS[nj][2],cS[nj][3]));
        }
        t0=fmaxf(t0,__shfl_xor_sync(0xffffffffu,t0,1));
        t0=fmaxf(t0,__shfl_xor_sync(0xffffffffu,t0,2));
        t1=fmaxf(t1,__shfl_xor_sync(0xffffffffu,t1,1));
        t1=fmaxf(t1,__shfl_xor_sync(0xffffffffu,t1,2));
        float mn0=fmaxf(m0,t0),mn1=fmaxf(m1,t1);
        float cor0=fast_exp(m0-mn0),cor1=fast_exp(m1-mn1);
        m0=mn0;m1=mn1;
        float s0=0.f,s1=0.f;
#pragma unroll
        for(int nj=0;nj<8;nj++){
            float p00=fast_exp(cS[nj][0]-m0), p01=fast_exp(cS[nj][1]-m0);
            float p10=fast_exp(cS[nj][2]-m1), p11=fast_exp(cS[nj][3]-m1);
            s0+=p00+p01; s1+=p10+p11;
            int colp=nj*8+2*qc;
            myP[qr*PS3+colp]=to_tf32(p00);     myP[qr*PS3+colp+1]=to_tf32(p01);
            myP[(qr+8)*PS3+colp]=to_tf32(p10); myP[(qr+8)*PS3+colp+1]=to_tf32(p11);
        }
        s0+=__shfl_xor_sync(0xffffffffu,s0,1); s0+=__shfl_xor_sync(0xffffffffu,s0,2);
        s1+=__shfl_xor_sync(0xffffffffu,s1,1); s1+=__shfl_xor_sync(0xffffffffu,s1,2);
        l0=l0*cor0+s0; l1=l1*cor1+s1;
#pragma unroll
        for(int nd=0;nd<4;nd++){
            cO[nd][0]*=cor0; cO[nd][1]*=cor0; cO[nd][2]*=cor1; cO[nd][3]*=cor1;
        }
        __syncwarp();
#pragma unroll
        for(int ksp=0;ksp<8;ksp++){
            int pc=ksp*8+qc;
            unsigned aP[4];
            aP[0]=__float_as_uint(myP[qr*PS3+pc]);
            aP[1]=__float_as_uint(myP[(qr+8)*PS3+pc]);
            aP[2]=__float_as_uint(myP[qr*PS3+pc+4]);
            aP[3]=__float_as_uint(myP[(qr+8)*PS3+pc+4]);
#pragma unroll
            for(int nd=0;nd<4;nd++){
                int dc=nd*8+qr;
                unsigned bf[2];
                bf[0]=__float_as_uint(fV[dc*KS3+pc]);
                bf[1]=__float_as_uint(fV[dc*KS3+pc+4]);
                mma_tf32(cO[nd],aP,bf);
            }
        }
        __syncwarp();
    }
    float il0=1.f/l0, il1=1.f/l1;
    size_t obase=((size_t)b*C+h*HDIM)*HW;
#pragma unroll
    for(int nd=0;nd<4;nd++){
        int d=nd*8+2*qc;
        out[obase+(size_t)d*HW+q0+qr]=to_tf32(cO[nd][0]*il0);
        out[obase+(size_t)(d+1)*HW+q0+qr]=to_tf32(cO[nd][1]*il0);
        out[obase+(size_t)d*HW+q0+qr+8]=to_tf32(cO[nd][2]*il1);
        out[obase+(size_t)(d+1)*HW+q0+qr+8]=to_tf32(cO[nd][3]*il1);
    }
}

extern "C" void kernel_launch(void* const* d_in, const int* in_sizes, int n_in,
                              void* d_out, int out_size)
{
    const float* x=(const float*)d_in[0];
    const float* c1w=(const float*)d_in[1]; const float* c1b=(const float*)d_in[2];
    const float* g1=(const float*)d_in[3];  const float* be1=(const float*)d_in[4];
    const float* m1=(const float*)d_in[5];  const float* v1=(const float*)d_in[6];
    const float* c2w=(const float*)d_in[7]; const float* c2b=(const float*)d_in[8];
    const float* g2=(const float*)d_in[9];  const float* be2=(const float*)d_in[10];
    const float* m2=(const float*)d_in[11]; const float* v2=(const float*)d_in[12];
    const float* q_w=(const float*)d_in[13];const float* q_b=(const float*)d_in[14];
    const float* k_w=(const float*)d_in[15];const float* k_b=(const float*)d_in[16];
    const float* v_w=(const float*)d_in[17];const float* v_b=(const float*)d_in[18];
    const float* o_w=(const float*)d_in[19];const float* o_b=(const float*)d_in[20];
    const float* gate=(const float*)d_in[21];
    float* out=(float*)d_out;

    float *p_b1,*p_b2,*p_wqkv,*p_bqkv,*p_wot,*p_conv,*p_qkv,*p_attn;
    __half *p_w1f,*p_w2f,*p_t1f;
    uint32_t *p_px0,*p_pxm,*p_pxp,*p_pt0,*p_ptm,*p_ptp;
    cudaGetSymbolAddress((void**)&p_b1,g_b1);
    cudaGetSymbolAddress((void**)&p_b2,g_b2);
    cudaGetSymbolAddress((void**)&p_wqkv,g_wqkv);
    cudaGetSymbolAddress((void**)&p_bqkv,g_bqkv);
    cudaGetSymbolAddress((void**)&p_wot,g_wot);
    cudaGetSymbolAddress((void**)&p_conv,g_conv);
    cudaGetSymbolAddress((void**)&p_qkv,g_qkv);
    cudaGetSymbolAddress((void**)&p_attn,g_attn);
    cudaGetSymbolAddress((void**)&p_w1f,g_w1f);
    cudaGetSymbolAddress((void**)&p_w2f,g_w2f);
    cudaGetSymbolAddress((void**)&p_t1f,g_t1f);
    cudaGetSymbolAddress((void**)&p_px0,g_px0);
    cudaGetSymbolAddress((void**)&p_pxm,g_pxm);
    cudaGetSymbolAddress((void**)&p_pxp,g_pxp);
    cudaGetSymbolAddress((void**)&p_pt0,g_pt0);
    cudaGetSymbolAddress((void**)&p_ptm,g_ptm);
    cudaGetSymbolAddress((void**)&p_ptp,g_ptp);

    static cudaStream_t s_side=nullptr;
    static cudaEvent_t ev_fork=nullptr, ev_join=nullptr;
    static bool attrs_set=false;
    if(s_side==nullptr){
        cudaStreamCreateWithFlags(&s_side,cudaStreamNonBlocking);
        cudaEventCreateWithFlags(&ev_fork,cudaEventDisableTiming);
        cudaEventCreateWithFlags(&ev_join,cudaEventDisableTiming);
    }
    if(!attrs_set){
        cudaFuncSetAttribute(gemm_k<0,1>,cudaFuncAttributeMaxDynamicSharedMemorySize,GEMM_SMEM);
        cudaFuncSetAttribute(gemm_k<2,0>,cudaFuncAttributeMaxDynamicSharedMemorySize,GEMM_SMEM);
        cudaFuncSetAttribute(convf16_k<1>,cudaFuncAttributeMaxDynamicSharedMemorySize,CONV_SMEM);
        cudaFuncSetAttribute(convf16_k<0>,cudaFuncAttributeMaxDynamicSharedMemorySize,CONV_SMEM);
        cudaFuncSetAttribute(fattn_kernel,cudaFuncAttributeMaxDynamicSharedMemorySize,FATTN_SMEM);
        attrs_set=true;
    }

    // side: pack x; main: prep
    xpack_kernel<<<NPAIR/256,256,0,s_side>>>(x);
    prep_kernel<<<1024,256>>>(c1w,c1b,g1,be1,m1,v1,c2w,c2b,g2,be2,m2,v2,
                              q_w,q_b,k_w,k_b,v_w,v_b,o_w);
    cudaEventRecord(ev_fork,0);
    cudaStreamWaitEvent(s_side,ev_fork,0);

    dim3 gConv(BATCH*8, 2);
    convf16_k<1><<<gConv,256,CONV_SMEM,s_side>>>(
        p_w1f, p_px0,p_pxm,p_pxp, p_b1, nullptr, p_t1f);
    tpack_kernel<<<NPAIR/256,256,0,s_side>>>(p_t1f);
    convf16_k<0><<<gConv,256,CONV_SMEM,s_side>>>(
        p_w2f, p_pt0,p_ptm,p_ptp, p_b2, p_conv, nullptr);
    cudaEventRecord(ev_join,s_side);

    dim3 gQKV(M_TOTAL/BM, 768/BN);
    gemm_k<0,1><<<gQKV,256,GEMM_SMEM>>>(x,p_wqkv,p_bqkv,p_qkv,C,768,
                                        nullptr,nullptr,nullptr);
    dim3 gAttn(HW/64, HEADS, BATCH);
    fattn_kernel<<<gAttn,128,FATTN_SMEM>>>(p_qkv,p_attn);

    cudaStreamWaitEvent(0,ev_join,0);
    dim3 gOut(M_TOTAL/BM, C/BN);
    gemm_k<2,0><<<gOut,256,GEMM_SMEM>>>(p_attn,p_wot,o_b,out,C,C,
                                        p_conv,x,gate);
}